// round 1
// baseline (speedup 1.0000x reference)
#include <cuda_runtime.h>
#include <cuda_bf16.h>
#include <math.h>

#define NNODES 3070
#define NFEAT 128
#define NOUT 64
#define HS 50
#define NEDGES 49120
#define NB 128

// ---------------- device scratch (static, no allocations) ----------------
__device__ int   g_is64;
__device__ int   g_present[NNODES];
__device__ int   g_rank[NNODES];
__device__ float g_deg[NNODES];
__device__ float g_dinv[NNODES];
__device__ int   g_counts[NNODES];
__device__ int   g_csrptr[NNODES + 1];
__device__ int   g_cursor[NNODES];
__device__ int   g_esrc[NEDGES];
__device__ int   g_edst[NEDGES];
__device__ int   g_csrc[NEDGES];
__device__ float g_cw[NEDGES];
__device__ float g_M[NFEAT * HS];     // M = W @ W_ih^T  (128 x 50)
__device__ float g_cvec[HS];          // c = b @ W_ih^T + b_ih
__device__ float g_u[(size_t)NB * NNODES * HS];    // x @ M
__device__ float g_pre[(size_t)NB * NNODES * HS];  // A @ u + c

// ---------------- setup: zero / detect dtype / fold weights ----------------
__global__ void k_setup(const void* eidx, const float* __restrict__ W,
                        const float* __restrict__ b,
                        const float* __restrict__ W_ih,
                        const float* __restrict__ b_ih) {
    int tid = blockIdx.x * blockDim.x + threadIdx.x;
    if (tid == 0) {
        // If edge_index is int64, the high 32-bit words (odd int32 positions)
        // are all zero (values < 3070). If int32, odd positions are node ids
        // and are ~never all zero over 256 samples.
        const int* p = (const int*)eidx;
        int is64 = 1;
        for (int i = 1; i < 512; i += 2) {
            if (p[i] != 0) { is64 = 0; break; }
        }
        g_is64 = is64;
    }
    if (tid < NNODES) {
        g_present[tid] = 0;
        g_deg[tid] = 1.0f;   // self-loop weight pre-added
        g_counts[tid] = 0;
    }
    int mi = tid - 4096;
    if (mi >= 0 && mi < NFEAT * HS) {
        int f = mi / HS, j = mi - f * HS;
        float s = 0.f;
        #pragma unroll 8
        for (int o = 0; o < NOUT; o++) s += W[f * NOUT + o] * W_ih[j * NOUT + o];
        g_M[mi] = s;
    }
    int ci = tid - 12000;
    if (ci >= 0 && ci < HS) {
        float s = b_ih[ci];
        #pragma unroll 8
        for (int o = 0; o < NOUT; o++) s += b[o] * W_ih[ci * NOUT + o];
        g_cvec[ci] = s;
    }
}

__device__ __forceinline__ int load_eid(const void* eidx, int i, int is64) {
    if (is64) return (int)((const long long*)eidx)[i];
    return ((const int*)eidx)[i];
}

// ---------------- mark present node ids ----------------
__global__ void k_mark(const void* eidx) {
    int i = blockIdx.x * 256 + threadIdx.x;
    if (i >= 2 * NEDGES) return;
    int v = load_eid(eidx, i, g_is64);
    g_present[v] = 1;  // benign races (same value)
}

// ---------------- single-block exclusive scans ----------------
// mode 0: present -> rank (searchsorted remap)
// mode 1: counts  -> csrptr/cursor; also dinv = rsqrt(deg)
__global__ void k_scan(int mode) {
    __shared__ int sa[1024], sb[1024];
    int t = threadIdx.x;
    int base = t * 3;
    const int* in = mode ? g_counts : g_present;
    int v0 = (base     < NNODES) ? in[base]     : 0;
    int v1 = (base + 1 < NNODES) ? in[base + 1] : 0;
    int v2 = (base + 2 < NNODES) ? in[base + 2] : 0;
    int s = v0 + v1 + v2;
    sa[t] = s;
    __syncthreads();
    int* src = sa; int* dst = sb;
    for (int off = 1; off < 1024; off <<= 1) {
        int val = src[t];
        if (t >= off) val += src[t - off];
        dst[t] = val;
        __syncthreads();
        int* tmp = src; src = dst; dst = tmp;
    }
    int incl = src[t];
    int excl = incl - s;
    if (mode == 0) {
        if (base     < NNODES) g_rank[base]     = excl;
        if (base + 1 < NNODES) g_rank[base + 1] = excl + v0;
        if (base + 2 < NNODES) g_rank[base + 2] = excl + v0 + v1;
    } else {
        if (base < NNODES) {
            g_csrptr[base] = excl; g_cursor[base] = excl;
            g_dinv[base] = rsqrtf(g_deg[base]);
        }
        if (base + 1 < NNODES) {
            g_csrptr[base + 1] = excl + v0; g_cursor[base + 1] = excl + v0;
            g_dinv[base + 1] = rsqrtf(g_deg[base + 1]);
        }
        if (base + 2 < NNODES) {
            g_csrptr[base + 2] = excl + v0 + v1; g_cursor[base + 2] = excl + v0 + v1;
            g_dinv[base + 2] = rsqrtf(g_deg[base + 2]);
        }
        if (t == 1023) g_csrptr[NNODES] = incl;
    }
}

// ---------------- remap edges + degree/counts ----------------
__global__ void k_edges(const void* eidx, const float* __restrict__ ew) {
    int e = blockIdx.x * 256 + threadIdx.x;
    if (e >= NEDGES) return;
    int is64 = g_is64;
    int sid = load_eid(eidx, e, is64);
    int did = load_eid(eidx, NEDGES + e, is64);
    int s = g_rank[sid], d = g_rank[did];
    g_esrc[e] = s;
    g_edst[e] = d;
    atomicAdd(&g_deg[d], ew[e]);
    atomicAdd(&g_counts[d], 1);
}

// ---------------- fill CSR (by dst) with normalized weights ----------------
__global__ void k_fill(const float* __restrict__ ew) {
    int e = blockIdx.x * 256 + threadIdx.x;
    if (e >= NEDGES) return;
    int d = g_edst[e], s = g_esrc[e];
    int pos = atomicAdd(&g_cursor[d], 1);
    g_csrc[pos] = s;
    g_cw[pos] = g_dinv[s] * ew[e] * g_dinv[d];
}

// ---------------- GEMM: u = x @ M  (392960 x 128) @ (128 x 50) ----------------
// 3070 CTAs x 160 threads; thread tile 4 rows x 10 cols.
#define XS_STRIDE 133
#define GEMM_SMEM ((128 * XS_STRIDE + NFEAT * HS) * 4)
__global__ void __launch_bounds__(160) k_gemm(const float* __restrict__ x) {
    extern __shared__ float sm[];
    float* xs = sm;                    // 128 x 133 (padded)
    float* Ms = sm + 128 * XS_STRIDE;  // 128 x 50
    int t = threadIdx.x;
    for (int i = t; i < NFEAT * HS; i += 160) Ms[i] = g_M[i];
    size_t rowbase = (size_t)blockIdx.x * 128;
    const float4* x4 = (const float4*)(x + rowbase * NFEAT);
    for (int i = t; i < 128 * 32; i += 160) {
        int r = i >> 5, c = i & 31;
        float4 v = x4[(size_t)r * 32 + c];
        float* dp = &xs[r * XS_STRIDE + c * 4];
        dp[0] = v.x; dp[1] = v.y; dp[2] = v.z; dp[3] = v.w;
    }
    __syncthreads();
    int rblk = t / 5, cblk = t - rblk * 5;  // rows 4*rblk.., cols 10*cblk..
    float acc[4][10];
    #pragma unroll
    for (int i = 0; i < 4; i++)
        #pragma unroll
        for (int j = 0; j < 10; j++) acc[i][j] = 0.f;
    const float* xp = &xs[(4 * rblk) * XS_STRIDE];
    const float* mp = &Ms[cblk * 10];
    #pragma unroll 2
    for (int k = 0; k < 128; k++) {
        float xv0 = xp[k];
        float xv1 = xp[XS_STRIDE + k];
        float xv2 = xp[2 * XS_STRIDE + k];
        float xv3 = xp[3 * XS_STRIDE + k];
        const float* mk = &mp[k * HS];
        #pragma unroll
        for (int j = 0; j < 10; j++) {
            float mv = mk[j];
            acc[0][j] += xv0 * mv;
            acc[1][j] += xv1 * mv;
            acc[2][j] += xv2 * mv;
            acc[3][j] += xv3 * mv;
        }
    }
    __syncthreads();
    // stage through smem for coalesced store
    #pragma unroll
    for (int i = 0; i < 4; i++)
        #pragma unroll
        for (int j = 0; j < 10; j++)
            xs[(4 * rblk + i) * HS + cblk * 10 + j] = acc[i][j];
    __syncthreads();
    float* uo = g_u + rowbase * HS;
    for (int i = t; i < 128 * HS; i += 160) uo[i] = xs[i];
}

// ---------------- SpMM: pre[b,n,:] = sum_e w_e * u[b,src_e,:] + dinv[n]^2*u[b,n,:] + c
// warp per (b, n); lanes 0..31 handle col lane, lanes 0..17 also col 32+lane.
__global__ void k_spmm() {
    int gw = blockIdx.x * 8 + (threadIdx.x >> 5);
    int lane = threadIdx.x & 31;
    int b = gw / NNODES;
    int n = gw - b * NNODES;
    const float* ub = g_u + (size_t)b * NNODES * HS;
    int e0 = g_csrptr[n], e1 = g_csrptr[n + 1];
    bool hi = lane < 18;
    int l1 = hi ? 32 + lane : lane;
    float acc0 = 0.f, acc1 = 0.f;
    for (int e = e0; e < e1; e++) {
        int s = g_csrc[e];
        float wv = g_cw[e];
        const float* ur = ub + (size_t)s * HS;
        acc0 += wv * ur[lane];
        acc1 += wv * ur[l1];
    }
    float dv = g_dinv[n];
    float ws = dv * dv;  // self-loop norm
    const float* un = ub + (size_t)n * HS;
    acc0 += ws * un[lane];
    acc1 += ws * un[l1];
    float* pr = g_pre + (size_t)gw * HS;
    pr[lane] = acc0 + g_cvec[lane];
    if (hi) pr[32 + lane] = acc1 + g_cvec[32 + lane];
}

// ---------------- RNN: per-node independent 128-step recurrence ----------------
__global__ void __launch_bounds__(256) k_rnn(const float* __restrict__ Whh,
                                             const float* __restrict__ bhh,
                                             const float* __restrict__ h0,
                                             float* __restrict__ out) {
    int w = blockIdx.x * 8 + (threadIdx.x >> 5);
    int lane = threadIdx.x & 31;
    if (w >= NNODES) return;
    __shared__ float hsm[8][64];
    float* h = hsm[threadIdx.x >> 5];
    bool hi = lane < 18;
    int c1 = hi ? 32 + lane : 0;
    float w0[HS], w1[HS];
    #pragma unroll
    for (int k = 0; k < HS; k++) {
        w0[k] = Whh[lane * HS + k];  // row 'lane' of W_hh -> output col lane
        w1[k] = Whh[c1 * HS + k];
    }
    float b0 = bhh[lane];
    float b1 = bhh[c1];
    h[lane] = h0[(size_t)w * HS + lane];
    if (hi) h[32 + lane] = h0[(size_t)w * HS + 32 + lane];
    __syncwarp();
    const float* prew = g_pre + (size_t)w * HS;
    float* outw = out + (size_t)w * HS;
    const size_t stride = (size_t)NNODES * HS;
    for (int t = 0; t < NB; t++) {
        float a0 = prew[lane] + b0;
        float a1 = hi ? (prew[32 + lane] + b1) : 0.f;
        float p0 = 0.f, q0 = 0.f, p1 = 0.f, q1 = 0.f;
        #pragma unroll
        for (int k = 0; k < HS; k += 2) {
            float hk = h[k], hk2 = h[k + 1];
            p0 += hk * w0[k];  q0 += hk2 * w0[k + 1];
            p1 += hk * w1[k];  q1 += hk2 * w1[k + 1];
        }
        a0 += p0 + q0;
        a1 += p1 + q1;
        float t0 = tanhf(a0);
        float t1 = tanhf(a1);
        __syncwarp();
        h[lane] = t0;
        if (hi) h[32 + lane] = t1;
        __syncwarp();
        outw[lane] = t0;
        if (hi) outw[32 + lane] = t1;
        prew += stride;
        outw += stride;
    }
}

// ---------------- launch ----------------
extern "C" void kernel_launch(void* const* d_in, const int* in_sizes, int n_in,
                              void* d_out, int out_size) {
    const float* x    = (const float*)d_in[0];
    const void*  eidx = d_in[1];
    const float* ew   = (const float*)d_in[2];
    const float* W    = (const float*)d_in[3];
    const float* b    = (const float*)d_in[4];
    const float* W_ih = (const float*)d_in[5];
    const float* W_hh = (const float*)d_in[6];
    const float* b_ih = (const float*)d_in[7];
    const float* b_hh = (const float*)d_in[8];
    const float* h0   = (const float*)d_in[9];
    float* out = (float*)d_out;

    cudaFuncSetAttribute(k_gemm, cudaFuncAttributeMaxDynamicSharedMemorySize,
                         GEMM_SMEM);

    k_setup<<<64, 256>>>(eidx, W, b, W_ih, b_ih);
    k_mark<<<(2 * NEDGES + 255) / 256, 256>>>(eidx);
    k_scan<<<1, 1024>>>(0);
    k_edges<<<(NEDGES + 255) / 256, 256>>>(eidx, ew);
    k_scan<<<1, 1024>>>(1);
    k_fill<<<(NEDGES + 255) / 256, 256>>>(ew);
    k_gemm<<<NNODES, 160, GEMM_SMEM>>>(x);
    k_spmm<<<(NB * NNODES) / 8, 256>>>();
    k_rnn<<<(NNODES + 7) / 8, 256>>>(W_hh, b_hh, h0, out);
}